// round 6
// baseline (speedup 1.0000x reference)
#include <cuda_runtime.h>

// w: [4096, 4096] fp32. Hinv1 dead (LAMBDA=1.0), bit_width fixed at 3.
#define NROWS 4096
#define NCOLS 4096
#define NTHREADS 256
#define EPT (NCOLS / NTHREADS)
#define NCAND 101

__device__ __forceinline__ float fast_lg2(float x) {
    float y; asm("lg2.approx.f32 %0, %1;" : "=f"(y) : "f"(x)); return y;
}
__device__ __forceinline__ float fast_ex2(float x) {
    float y; asm("ex2.approx.f32 %0, %1;" : "=f"(y) : "f"(x)); return y;
}

// ---- packed f32x2 helpers (Blackwell sm_103a) ----
__device__ __forceinline__ unsigned long long pk2(float lo, float hi) {
    unsigned long long o;
    asm("mov.b64 %0, {%1, %2};" : "=l"(o) : "f"(lo), "f"(hi));
    return o;
}
__device__ __forceinline__ void upk2(float& lo, float& hi, unsigned long long p) {
    asm("mov.b64 {%0, %1}, %2;" : "=f"(lo), "=f"(hi) : "l"(p));
}
__device__ __forceinline__ unsigned long long mul2(unsigned long long a, unsigned long long b) {
    unsigned long long o;
    asm("mul.rn.f32x2 %0, %1, %2;" : "=l"(o) : "l"(a), "l"(b));
    return o;
}
__device__ __forceinline__ unsigned long long add2(unsigned long long a, unsigned long long b) {
    unsigned long long o;
    asm("add.rn.f32x2 %0, %1, %2;" : "=l"(o) : "l"(a), "l"(b));
    return o;
}
__device__ __forceinline__ unsigned long long fma2(unsigned long long a, unsigned long long b,
                                                   unsigned long long c) {
    unsigned long long o;
    asm("fma.rn.f32x2 %0, %1, %2, %3;" : "=l"(o) : "l"(a), "l"(b), "l"(c));
    return o;
}
// |.| on both packed halves (clear sign bits)
__device__ __forceinline__ unsigned long long abs2(unsigned long long a) {
    return a & 0x7FFFFFFF7FFFFFFFull;
}

// ---- f16x2 MUFU helpers ----
__device__ __forceinline__ unsigned cvt_f16x2(float hi, float lo) {
    unsigned r; asm("cvt.rn.f16x2.f32 %0, %1, %2;" : "=r"(r) : "f"(hi), "f"(lo));
    return r;
}
__device__ __forceinline__ unsigned ex2h2(unsigned x) {
    unsigned r; asm("ex2.approx.f16x2 %0, %1;" : "=r"(r) : "r"(x));
    return r;
}
__device__ __forceinline__ void h2_to_f32(float& lo, float& hi, unsigned h) {
    asm("{\n\t.reg .b16 l, u;\n\t"
        "mov.b32 {l, u}, %2;\n\t"
        "cvt.f32.f16 %0, l;\n\t"
        "cvt.f32.f16 %1, u;\n\t}" : "=f"(lo), "=f"(hi) : "r"(h));
}

// Candidate shrink factors in reference scan order.
__device__ __forceinline__ float pcand(int c) {
    const float delta = 0.1f / 50.0f;
    if (c == 0) return 1.0f;
    if (c <= 50) return fmaf(delta, (float)c, 1.0f);
    return fmaf(-delta, (float)(c - 50), 1.0f);
}

#define MAGIC 12582912.0f   // 1.5*2^23

// Degree-6 Chebyshev-economized poly for x^2.4 on [0,1], abs err <= ~5e-5.
#define PA0  0.0000551f
#define PA1 -0.0078023f
#define PA2  0.3638754f
#define PA3  1.1643678f
#define PA4 -0.9356587f
#define PA5  0.5629952f
#define PA6 -0.1478570f

__device__ __forceinline__ float poly24(float at) {   // P(|t|) ~= |t|^2.4
    float p = PA6;
    p = fmaf(p, at, PA5);
    p = fmaf(p, at, PA4);
    p = fmaf(p, at, PA3);
    p = fmaf(p, at, PA2);
    p = fmaf(p, at, PA1);
    p = fmaf(p, at, PA0);
    return p;
}

__global__ __launch_bounds__(NTHREADS, 4) void quant_search_kernel(
    const float* __restrict__ w, float* __restrict__ out)
{
    __shared__ __align__(16) float sact[NCOLS];  // interior front, boundary back
    __shared__ float sS[NCAND];
    __shared__ float sI[NCAND];
    __shared__ float sC[NCAND];                  // (s/2)^2.4 * 2^B per candidate
    __shared__ float serr[NCAND * 8];
    __shared__ float stot[NCAND];
    __shared__ float smn[8], smx[8];
    __shared__ float sscale;
    __shared__ int   scnt_i, scnt_b;

    const int row  = blockIdx.x;
    const int tid  = threadIdx.x;
    const int lane = tid & 31;
    const int wid  = tid >> 5;
    const float* __restrict__ wrow = w + (size_t)row * NCOLS;

    if (tid == 0) { scnt_i = 0; scnt_b = 0; }

    // ---- Load row; min/max vs 0 (reference semantics) ----
    float wv[EPT];
    float mn = 0.0f, mx = 0.0f;
    #pragma unroll
    for (int k = 0; k < EPT; k++) {
        wv[k] = wrow[tid + k * NTHREADS];
        mn = fminf(mn, wv[k]);
        mx = fmaxf(mx, wv[k]);
    }
    #pragma unroll
    for (int o = 16; o > 0; o >>= 1) {
        mn = fminf(mn, __shfl_xor_sync(0xffffffffu, mn, o));
        mx = fmaxf(mx, __shfl_xor_sync(0xffffffffu, mx, o));
    }
    if (lane == 0) { smn[wid] = mn; smx[wid] = mx; }
    __syncthreads();

    float xmin = smn[0], xmax = smx[0];
    #pragma unroll
    for (int k = 1; k < 8; k++) {
        xmin = fminf(xmin, smn[k]);
        xmax = fmaxf(xmax, smx[k]);
    }
    if (xmin == 0.0f && xmax == 0.0f) { xmin = -1.0f; xmax = 1.0f; }
    const float rng = xmax - xmin;

    const float s_min = pcand(NCAND - 1) * rng / 7.0f;
    const float thr_p  = 0.49999f * s_min;   // prune: rint=0 for every candidate
    const float thr_hi = 3.4999f  * s_min;   // interior: clamp can never fire
    const float thr_lo = -4.4999f * s_min;

    // Per-row exponent bias (argmin-invariant global factor 2^B).
    const float B = fmaf(-2.4f, fast_lg2(rng), 11.5376f);

    if (tid < NCAND) {
        float s = pcand(tid) * rng / 7.0f;
        sS[tid] = s;
        sI[tid] = 1.0f / s;
        // Cc = (s/2)^2.4 * 2^B
        sC[tid] = fast_ex2(fmaf(2.4f, fast_lg2(0.5f * s), B));
    }

    // ---- Two-class compaction (order irrelevant to fp-tolerant argmin) ----
    int ci = 0, cb = 0;
    #pragma unroll
    for (int k = 0; k < EPT; k++) {
        bool active = fabsf(wv[k]) > thr_p;
        bool inter  = active && (wv[k] < thr_hi) && (wv[k] > thr_lo);
        ci += inter ? 1 : 0;
        cb += (active && !inter) ? 1 : 0;
    }
    int bi_ = (ci > 0) ? atomicAdd(&scnt_i, ci) : 0;
    int bb_ = (cb > 0) ? atomicAdd(&scnt_b, cb) : 0;
    #pragma unroll
    for (int k = 0; k < EPT; k++) {
        bool active = fabsf(wv[k]) > thr_p;
        bool inter  = active && (wv[k] < thr_hi) && (wv[k] > thr_lo);
        if (inter) sact[bi_++] = wv[k];
        else if (active) sact[NCOLS - 1 - (bb_++)] = wv[k];
    }
    __syncthreads();
    const int nint   = scnt_i;
    const int nbnd   = scnt_b;
    const int npairs = nint >> 1;
    const int oddi   = nint & 1;
    // Pipe-balance split: ~29% of pairs on the fma-pipe poly path, rest on MUFU f16 path.
    const int npoly  = (npairs * 19) >> 6;

    const unsigned long long MG  = pk2(MAGIC, MAGIC);
    const unsigned long long NMG = pk2(-MAGIC, -MAGIC);
    const unsigned long long M2  = pk2(-2.0f, -2.0f);
    const unsigned long long A0 = pk2(PA0, PA0), A1 = pk2(PA1, PA1), A2 = pk2(PA2, PA2);
    const unsigned long long A3 = pk2(PA3, PA3), A4 = pk2(PA4, PA4), A5 = pk2(PA5, PA5);
    const unsigned long long A6 = pk2(PA6, PA6);

    // ---- Candidate search: 25 tiles of 4, then candidate 100 ----
    for (int ct = 0; ct < NCAND - 1; ct += 4) {
        const float s0 = sS[ct],  s1 = sS[ct+1], s2 = sS[ct+2], s3 = sS[ct+3];
        const float i0 = sI[ct],  i1 = sI[ct+1], i2 = sI[ct+2], i3 = sI[ct+3];
        const float C0 = sC[ct],  C1 = sC[ct+1], C2 = sC[ct+2], C3 = sC[ct+3];
        const unsigned long long ii0 = pk2(i0, i0), ii1 = pk2(i1, i1);
        const unsigned long long ii2 = pk2(i2, i2), ii3 = pk2(i3, i3);

        // Phase 1: poly path (fma pipe, zero MUFU), raw accumulation of P(|t|)
        unsigned long long p0 = 0ull, p1 = 0ull, p2 = 0ull, p3 = 0ull;
        for (int i = tid; i < npoly; i += NTHREADS) {
            const float2 vp = reinterpret_cast<const float2*>(sact)[i];
            const unsigned long long v2 = pk2(vp.x, vp.y);
            #define POLY_STEP(ii, acc) do {                                   \
                unsigned long long u = mul2(v2, ii);                          \
                unsigned long long r = add2(add2(u, MG), NMG);                \
                unsigned long long t = fma2(r, M2, add2(u, u));  /* 2(u-r) */ \
                unsigned long long at = abs2(t);                              \
                unsigned long long q = fma2(A6, at, A5);                      \
                q = fma2(q, at, A4); q = fma2(q, at, A3);                     \
                q = fma2(q, at, A2); q = fma2(q, at, A1);                     \
                q = fma2(q, at, A0);                                          \
                acc = add2(acc, q); } while (0)
            POLY_STEP(ii0, p0);
            POLY_STEP(ii1, p1);
            POLY_STEP(ii2, p2);
            POLY_STEP(ii3, p3);
            #undef POLY_STEP
        }
        float a0, a1, a2, a3, tl, th;
        upk2(tl, th, p0); a0 = (tl + th) * C0;
        upk2(tl, th, p1); a1 = (tl + th) * C1;
        upk2(tl, th, p2); a2 = (tl + th) * C2;
        upk2(tl, th, p3); a3 = (tl + th) * C3;

        // Phase 2: f16-MUFU path on remaining pairs (pre-scaled by 2^B via +B)
        {
            const unsigned long long ns0 = pk2(-s0, -s0), ns1 = pk2(-s1, -s1);
            const unsigned long long ns2 = pk2(-s2, -s2), ns3 = pk2(-s3, -s3);
            unsigned long long f0 = 0ull, f1 = 0ull, f2 = 0ull, f3 = 0ull;
            for (int i = npoly + tid; i < npairs; i += NTHREADS) {
                const float2 vp = reinterpret_cast<const float2*>(sact)[i];
                const unsigned long long v2 = pk2(vp.x, vp.y);
                #define F16_STEP(ii, ns, acc) do {                             \
                    unsigned long long u = mul2(v2, ii);                       \
                    unsigned long long r = add2(add2(u, MG), NMG);             \
                    unsigned long long d = fma2(ns, r, v2);                    \
                    float dl, dh; upk2(dl, dh, d);                             \
                    float x0 = fmaf(2.4f, fast_lg2(fabsf(dl)), B);             \
                    float x1 = fmaf(2.4f, fast_lg2(fabsf(dh)), B);             \
                    float e0, e1; h2_to_f32(e0, e1, ex2h2(cvt_f16x2(x1, x0))); \
                    acc = add2(acc, pk2(e0, e1)); } while (0)
                F16_STEP(ii0, ns0, f0);
                F16_STEP(ii1, ns1, f1);
                F16_STEP(ii2, ns2, f2);
                F16_STEP(ii3, ns3, f3);
                #undef F16_STEP
            }
            upk2(tl, th, f0); a0 += tl + th;
            upk2(tl, th, f1); a1 += tl + th;
            upk2(tl, th, f2); a2 += tl + th;
            upk2(tl, th, f3); a3 += tl + th;
        }

        // Boundary (+ odd interior tail): scalar f32 MUFU with clamps, biased.
        for (int j = tid; j < nbnd + oddi; j += NTHREADS) {
            const float v = (j < nbnd) ? sact[NCOLS - 1 - j] : sact[nint - 1];
            float r;
            r = fminf(fmaxf(rintf(v * i0), -4.0f), 3.0f);
            a0 += fast_ex2(fmaf(2.4f, fast_lg2(fabsf(fmaf(s0, r, -v))), B));
            r = fminf(fmaxf(rintf(v * i1), -4.0f), 3.0f);
            a1 += fast_ex2(fmaf(2.4f, fast_lg2(fabsf(fmaf(s1, r, -v))), B));
            r = fminf(fmaxf(rintf(v * i2), -4.0f), 3.0f);
            a2 += fast_ex2(fmaf(2.4f, fast_lg2(fabsf(fmaf(s2, r, -v))), B));
            r = fminf(fmaxf(rintf(v * i3), -4.0f), 3.0f);
            a3 += fast_ex2(fmaf(2.4f, fast_lg2(fabsf(fmaf(s3, r, -v))), B));
        }

        #pragma unroll
        for (int o = 16; o > 0; o >>= 1) {
            a0 += __shfl_xor_sync(0xffffffffu, a0, o);
            a1 += __shfl_xor_sync(0xffffffffu, a1, o);
            a2 += __shfl_xor_sync(0xffffffffu, a2, o);
            a3 += __shfl_xor_sync(0xffffffffu, a3, o);
        }
        if (lane == 0) {
            serr[(ct    ) * 8 + wid] = a0;
            serr[(ct + 1) * 8 + wid] = a1;
            serr[(ct + 2) * 8 + wid] = a2;
            serr[(ct + 3) * 8 + wid] = a3;
        }
    }
    {   // candidate 100: scalar, mirrors the segment treatment
        const int c = NCAND - 1;
        const float s = sS[c], is = sI[c], Cc = sC[c];
        float araw = 0.0f, a = 0.0f;
        const int epoly = npoly * 2;                 // poly segment in elements
        for (int i = tid; i < epoly; i += NTHREADS) {
            const float v = sact[i];
            float u = v * is;
            float r = rintf(u);
            float t = fabsf(2.0f * (u - r));
            araw += poly24(t);
        }
        a = araw * Cc;
        for (int i = epoly + tid; i < nint; i += NTHREADS) {
            const float v = sact[i];
            float r = rintf(v * is);
            a += fast_ex2(fmaf(2.4f, fast_lg2(fabsf(fmaf(s, r, -v))), B));
        }
        for (int j = tid; j < nbnd; j += NTHREADS) {
            const float v = sact[NCOLS - 1 - j];
            float r = fminf(fmaxf(rintf(v * is), -4.0f), 3.0f);
            a += fast_ex2(fmaf(2.4f, fast_lg2(fabsf(fmaf(s, r, -v))), B));
        }
        #pragma unroll
        for (int o = 16; o > 0; o >>= 1) a += __shfl_xor_sync(0xffffffffu, a, o);
        if (lane == 0) serr[c * 8 + wid] = a;
    }
    __syncthreads();

    if (tid < NCAND) {
        float t = 0.0f;
        #pragma unroll
        for (int k = 0; k < 8; k++) t += serr[tid * 8 + k];
        stot[tid] = t;
    }
    __syncthreads();

    if (tid == 0) {
        float best = stot[0];
        int bi = 0;
        for (int c = 1; c < NCAND; c++) {
            float e = stot[c];
            if (e < best) { best = e; bi = c; }
        }
        sscale = sS[bi];
    }
    __syncthreads();

    // ---- Final dequant (re-read row from gmem) ----
    const float s    = sscale;
    const float invs = 1.0f / s;
    float* __restrict__ orow = out + (size_t)row * NCOLS;
    #pragma unroll
    for (int k = 0; k < EPT; k++) {
        float v = wrow[tid + k * NTHREADS];
        float r = rintf(v * invs);
        r = fminf(fmaxf(r, -4.0f), 3.0f);
        orow[tid + k * NTHREADS] = s * r;
    }
}

extern "C" void kernel_launch(void* const* d_in, const int* in_sizes, int n_in,
                              void* d_out, int out_size) {
    (void)in_sizes; (void)n_in; (void)out_size;
    const float* w = (const float*)d_in[0];
    float* out = (float*)d_out;
    quant_search_kernel<<<NROWS, NTHREADS>>>(w, out);
}

// round 8
// speedup vs baseline: 1.0316x; 1.0316x over previous
#include <cuda_runtime.h>

// w: [4096, 4096] fp32. Hinv1 dead (LAMBDA=1.0), bit_width fixed at 3.
#define NROWS 4096
#define NCOLS 4096
#define NTHREADS 256
#define EPT (NCOLS / NTHREADS)
#define NCAND 101

__device__ __forceinline__ float fast_lg2(float x) {
    float y; asm("lg2.approx.f32 %0, %1;" : "=f"(y) : "f"(x)); return y;
}
__device__ __forceinline__ float fast_ex2(float x) {
    float y; asm("ex2.approx.f32 %0, %1;" : "=f"(y) : "f"(x)); return y;
}

// ---- packed f32x2 helpers (Blackwell sm_103a) ----
__device__ __forceinline__ unsigned long long pk2(float lo, float hi) {
    unsigned long long o;
    asm("mov.b64 %0, {%1, %2};" : "=l"(o) : "f"(lo), "f"(hi));
    return o;
}
__device__ __forceinline__ void upk2(float& lo, float& hi, unsigned long long p) {
    asm("mov.b64 {%0, %1}, %2;" : "=f"(lo), "=f"(hi) : "l"(p));
}
__device__ __forceinline__ unsigned long long mul2(unsigned long long a, unsigned long long b) {
    unsigned long long o;
    asm("mul.rn.f32x2 %0, %1, %2;" : "=l"(o) : "l"(a), "l"(b));
    return o;
}
__device__ __forceinline__ unsigned long long add2(unsigned long long a, unsigned long long b) {
    unsigned long long o;
    asm("add.rn.f32x2 %0, %1, %2;" : "=l"(o) : "l"(a), "l"(b));
    return o;
}
__device__ __forceinline__ unsigned long long fma2(unsigned long long a, unsigned long long b,
                                                   unsigned long long c) {
    unsigned long long o;
    asm("fma.rn.f32x2 %0, %1, %2, %3;" : "=l"(o) : "l"(a), "l"(b), "l"(c));
    return o;
}
__device__ __forceinline__ unsigned long long abs2(unsigned long long a) {
    return a & 0x7FFFFFFF7FFFFFFFull;
}

// ---- f16x2 MUFU helpers ----
__device__ __forceinline__ unsigned cvt_f16x2(float hi, float lo) {
    unsigned r; asm("cvt.rn.f16x2.f32 %0, %1, %2;" : "=r"(r) : "f"(hi), "f"(lo));
    return r;
}
__device__ __forceinline__ unsigned ex2h2(unsigned x) {
    unsigned r; asm("ex2.approx.f16x2 %0, %1;" : "=r"(r) : "r"(x));
    return r;
}
__device__ __forceinline__ void h2_to_f32(float& lo, float& hi, unsigned h) {
    asm("{\n\t.reg .b16 l, u;\n\t"
        "mov.b32 {l, u}, %2;\n\t"
        "cvt.f32.f16 %0, l;\n\t"
        "cvt.f32.f16 %1, u;\n\t}" : "=f"(lo), "=f"(hi) : "r"(h));
}

// Candidate shrink factors in reference scan order.
__device__ __forceinline__ float pcand(int c) {
    const float delta = 0.1f / 50.0f;
    if (c == 0) return 1.0f;
    if (c <= 50) return fmaf(delta, (float)c, 1.0f);
    return fmaf(-delta, (float)(c - 50), 1.0f);
}

#define MAGIC  12582912.0f   // 1.5*2^23 : scalar rint
#define MAGIC2 25165824.0f   // 3*2^23   : even-grain magic -> R = 2*rint(q/2)

// Degree-6 Chebyshev-economized poly for x^2.4 on [0,1], abs err <= ~5e-5.
#define PA0  0.0000551f
#define PA1 -0.0078023f
#define PA2  0.3638754f
#define PA3  1.1643678f
#define PA4 -0.9356587f
#define PA5  0.5629952f
#define PA6 -0.1478570f

__global__ __launch_bounds__(NTHREADS, 4) void quant_search_kernel(
    const float* __restrict__ w, float* __restrict__ out)
{
    __shared__ __align__(16) float sact[NCOLS];  // interior front, boundary back
    __shared__ float sS[NCAND];
    __shared__ float sI[NCAND];
    __shared__ float sC[NCAND];                  // (s/2)^2.4 * 2^B per candidate
    __shared__ float serr[NCAND * 8];
    __shared__ float stot[NCAND];
    __shared__ float smn[8], smx[8];
    __shared__ float sscale;
    __shared__ int   scnt_i, scnt_b;

    const int row  = blockIdx.x;
    const int tid  = threadIdx.x;
    const int lane = tid & 31;
    const int wid  = tid >> 5;
    const float* __restrict__ wrow = w + (size_t)row * NCOLS;

    if (tid == 0) { scnt_i = 0; scnt_b = 0; }

    // ---- Load row; min/max vs 0 (reference semantics) ----
    float wv[EPT];
    float mn = 0.0f, mx = 0.0f;
    #pragma unroll
    for (int k = 0; k < EPT; k++) {
        wv[k] = wrow[tid + k * NTHREADS];
        mn = fminf(mn, wv[k]);
        mx = fmaxf(mx, wv[k]);
    }
    #pragma unroll
    for (int o = 16; o > 0; o >>= 1) {
        mn = fminf(mn, __shfl_xor_sync(0xffffffffu, mn, o));
        mx = fmaxf(mx, __shfl_xor_sync(0xffffffffu, mx, o));
    }
    if (lane == 0) { smn[wid] = mn; smx[wid] = mx; }
    __syncthreads();

    float xmin = smn[0], xmax = smx[0];
    #pragma unroll
    for (int k = 1; k < 8; k++) {
        xmin = fminf(xmin, smn[k]);
        xmax = fmaxf(xmax, smx[k]);
    }
    if (xmin == 0.0f && xmax == 0.0f) { xmin = -1.0f; xmax = 1.0f; }
    const float rng = xmax - xmin;

    const float s_min = pcand(NCAND - 1) * rng / 7.0f;
    const float thr_p  = 0.49999f * s_min;   // prune: rint=0 for every candidate
    const float thr_hi = 3.4999f  * s_min;   // interior: clamp can never fire
    const float thr_lo = -4.4999f * s_min;

    // Per-row exponent bias (argmin-invariant global factor 2^B).
    const float B = fmaf(-2.4f, fast_lg2(rng), 11.5376f);

    if (tid < NCAND) {
        float s = pcand(tid) * rng / 7.0f;
        sS[tid] = s;
        sI[tid] = 1.0f / s;
        sC[tid] = fast_ex2(fmaf(2.4f, fast_lg2(0.5f * s), B));  // (s/2)^2.4 * 2^B
    }

    // ---- Two-class compaction (order irrelevant to fp-tolerant argmin) ----
    int ci = 0, cb = 0;
    #pragma unroll
    for (int k = 0; k < EPT; k++) {
        bool active = fabsf(wv[k]) > thr_p;
        bool inter  = active && (wv[k] < thr_hi) && (wv[k] > thr_lo);
        ci += inter ? 1 : 0;
        cb += (active && !inter) ? 1 : 0;
    }
    int bi_ = (ci > 0) ? atomicAdd(&scnt_i, ci) : 0;
    int bb_ = (cb > 0) ? atomicAdd(&scnt_b, cb) : 0;
    #pragma unroll
    for (int k = 0; k < EPT; k++) {
        bool active = fabsf(wv[k]) > thr_p;
        bool inter  = active && (wv[k] < thr_hi) && (wv[k] > thr_lo);
        if (inter) sact[bi_++] = wv[k];
        else if (active) sact[NCOLS - 1 - (bb_++)] = wv[k];
    }
    __syncthreads();
    const int nint   = scnt_i;
    const int nbnd   = scnt_b;
    const int npairs = nint >> 1;
    const int oddi   = nint & 1;
    // Pipe-balance split alpha = 5/16 of pairs on the poly (fma) path.
    const int npoly  = (npairs * 5) >> 4;

    if (wid < 4) {
        // ===== POLY warps (one per SMSP): pairs [0, npoly), 128 threads =====
        const int g = wid * 32 + lane;               // 0..127, stride 128
        const unsigned long long MG2  = pk2(MAGIC2, MAGIC2);
        const unsigned long long NMG2 = pk2(-MAGIC2, -MAGIC2);
        const unsigned long long M1N  = pk2(-1.0f, -1.0f);
        const unsigned long long A0 = pk2(PA0, PA0), A1 = pk2(PA1, PA1);
        const unsigned long long A2 = pk2(PA2, PA2), A3 = pk2(PA3, PA3);
        const unsigned long long A4 = pk2(PA4, PA4), A5 = pk2(PA5, PA5);
        const unsigned long long A6 = pk2(PA6, PA6);

        for (int ct = 0; ct < NCAND - 1; ct += 4) {
            const float d0 = 2.0f * sI[ct],   d1 = 2.0f * sI[ct+1];
            const float d2 = 2.0f * sI[ct+2], d3 = 2.0f * sI[ct+3];
            const unsigned long long jj0 = pk2(d0, d0), jj1 = pk2(d1, d1);
            const unsigned long long jj2 = pk2(d2, d2), jj3 = pk2(d3, d3);
            unsigned long long p0 = 0ull, p1 = 0ull, p2 = 0ull, p3 = 0ull;

            for (int i = g; i < npoly; i += 128) {
                const float2 vp = reinterpret_cast<const float2*>(sact)[i];
                const unsigned long long v2 = pk2(vp.x, vp.y);
                #define POLY_STEP(jj, acc) do {                                \
                    unsigned long long q = mul2(v2, jj);       /* 2u        */ \
                    unsigned long long R = add2(add2(q, MG2), NMG2); /* 2r  */ \
                    unsigned long long t = fma2(R, M1N, q);    /* 2(u-r)   */  \
                    unsigned long long at = abs2(t);                           \
                    unsigned long long pp = fma2(A6, at, A5);                  \
                    pp = fma2(pp, at, A4); pp = fma2(pp, at, A3);              \
                    pp = fma2(pp, at, A2); pp = fma2(pp, at, A1);              \
                    pp = fma2(pp, at, A0);                                     \
                    acc = add2(acc, pp); } while (0)
                POLY_STEP(jj0, p0);
                POLY_STEP(jj1, p1);
                POLY_STEP(jj2, p2);
                POLY_STEP(jj3, p3);
                #undef POLY_STEP
            }
            float a0, a1, a2, a3, tl, th;
            upk2(tl, th, p0); a0 = (tl + th) * sC[ct];
            upk2(tl, th, p1); a1 = (tl + th) * sC[ct+1];
            upk2(tl, th, p2); a2 = (tl + th) * sC[ct+2];
            upk2(tl, th, p3); a3 = (tl + th) * sC[ct+3];
            #pragma unroll
            for (int o = 16; o > 0; o >>= 1) {
                a0 += __shfl_xor_sync(0xffffffffu, a0, o);
                a1 += __shfl_xor_sync(0xffffffffu, a1, o);
                a2 += __shfl_xor_sync(0xffffffffu, a2, o);
                a3 += __shfl_xor_sync(0xffffffffu, a3, o);
            }
            if (lane == 0) {
                serr[(ct    ) * 8 + wid] = a0;
                serr[(ct + 1) * 8 + wid] = a1;
                serr[(ct + 2) * 8 + wid] = a2;
                serr[(ct + 3) * 8 + wid] = a3;
            }
        }
        {   // candidate 100, poly segment
            const int c = NCAND - 1;
            const float dj = 2.0f * sI[c];
            const unsigned long long jj = pk2(dj, dj);
            unsigned long long p = 0ull;
            for (int i = g; i < npoly; i += 128) {
                const float2 vp = reinterpret_cast<const float2*>(sact)[i];
                const unsigned long long v2 = pk2(vp.x, vp.y);
                unsigned long long q = mul2(v2, jj);
                unsigned long long R = add2(add2(q, MG2), NMG2);
                unsigned long long t = fma2(R, M1N, q);
                unsigned long long at = abs2(t);
                unsigned long long pp = fma2(A6, at, A5);
                pp = fma2(pp, at, A4); pp = fma2(pp, at, A3);
                pp = fma2(pp, at, A2); pp = fma2(pp, at, A1);
                pp = fma2(pp, at, A0);
                p = add2(p, pp);
            }
            float tl, th; upk2(tl, th, p);
            float a = (tl + th) * sC[c];
            #pragma unroll
            for (int o = 16; o > 0; o >>= 1) a += __shfl_xor_sync(0xffffffffu, a, o);
            if (lane == 0) serr[c * 8 + wid] = a;
        }
    } else {
        // ===== F16 warps (one per SMSP): pairs [npoly, npairs), 128 threads =
        const int g = (wid - 4) * 32 + lane;         // 0..127, stride 128
        const unsigned long long MG  = pk2(MAGIC, MAGIC);
        const unsigned long long NMG = pk2(-MAGIC, -MAGIC);

        for (int ct = 0; ct < NCAND - 1; ct += 4) {
            const float s0 = sS[ct],  s1 = sS[ct+1], s2 = sS[ct+2], s3 = sS[ct+3];
            const float i0 = sI[ct],  i1 = sI[ct+1], i2 = sI[ct+2], i3 = sI[ct+3];
            const unsigned long long ii0 = pk2(i0, i0), ii1 = pk2(i1, i1);
            const unsigned long long ii2 = pk2(i2, i2), ii3 = pk2(i3, i3);
            const unsigned long long ns0 = pk2(-s0, -s0), ns1 = pk2(-s1, -s1);
            const unsigned long long ns2 = pk2(-s2, -s2), ns3 = pk2(-s3, -s3);
            unsigned long long f0 = 0ull, f1 = 0ull, f2 = 0ull, f3 = 0ull;

            for (int i = npoly + g; i < npairs; i += 128) {
                const float2 vp = reinterpret_cast<const float2*>(sact)[i];
                const unsigned long long v2 = pk2(vp.x, vp.y);
                #define F16_STEP(ii, ns, acc) do {                             \
                    unsigned long long u = mul2(v2, ii);                       \
                    unsigned long long r = add2(add2(u, MG), NMG);             \
                    unsigned long long d = fma2(ns, r, v2);                    \
                    float dl, dh; upk2(dl, dh, d);                             \
                    float x0 = fmaf(2.4f, fast_lg2(fabsf(dl)), B);             \
                    float x1 = fmaf(2.4f, fast_lg2(fabsf(dh)), B);             \
                    float e0, e1; h2_to_f32(e0, e1, ex2h2(cvt_f16x2(x1, x0))); \
                    acc = add2(acc, pk2(e0, e1)); } while (0)
                F16_STEP(ii0, ns0, f0);
                F16_STEP(ii1, ns1, f1);
                F16_STEP(ii2, ns2, f2);
                F16_STEP(ii3, ns3, f3);
                #undef F16_STEP
            }
            float a0, a1, a2, a3, tl, th;
            upk2(tl, th, f0); a0 = tl + th;
            upk2(tl, th, f1); a1 = tl + th;
            upk2(tl, th, f2); a2 = tl + th;
            upk2(tl, th, f3); a3 = tl + th;

            // Boundary (+ odd interior tail): scalar f32 MUFU with clamps.
            for (int j = g; j < nbnd + oddi; j += 128) {
                const float v = (j < nbnd) ? sact[NCOLS - 1 - j] : sact[nint - 1];
                float r;
                r = fminf(fmaxf(rintf(v * i0), -4.0f), 3.0f);
                a0 += fast_ex2(fmaf(2.4f, fast_lg2(fabsf(fmaf(s0, r, -v))), B));
                r = fminf(fmaxf(rintf(v * i1), -4.0f), 3.0f);
                a1 += fast_ex2(fmaf(2.4f, fast_lg2(fabsf(fmaf(s1, r, -v))), B));
                r = fminf(fmaxf(rintf(v * i2), -4.0f), 3.0f);
                a2 += fast_ex2(fmaf(2.4f, fast_lg2(fabsf(fmaf(s2, r, -v))), B));
                r = fminf(fmaxf(rintf(v * i3), -4.0f), 3.0f);
                a3 += fast_ex2(fmaf(2.4f, fast_lg2(fabsf(fmaf(s3, r, -v))), B));
            }
            #pragma unroll
            for (int o = 16; o > 0; o >>= 1) {
                a0 += __shfl_xor_sync(0xffffffffu, a0, o);
                a1 += __shfl_xor_sync(0xffffffffu, a1, o);
                a2 += __shfl_xor_sync(0xffffffffu, a2, o);
                a3 += __shfl_xor_sync(0xffffffffu, a3, o);
            }
            if (lane == 0) {
                serr[(ct    ) * 8 + wid] = a0;
                serr[(ct + 1) * 8 + wid] = a1;
                serr[(ct + 2) * 8 + wid] = a2;
                serr[(ct + 3) * 8 + wid] = a3;
            }
        }
        {   // candidate 100, f16 segment + boundary
            const int c = NCAND - 1;
            const float s = sS[c], is = sI[c];
            float a = 0.0f;
            for (int i = 2 * npoly + g; i < nint; i += 128) {
                const float v = sact[i];
                float r = rintf(v * is);
                a += fast_ex2(fmaf(2.4f, fast_lg2(fabsf(fmaf(s, r, -v))), B));
            }
            for (int j = g; j < nbnd; j += 128) {
                const float v = sact[NCOLS - 1 - j];
                float r = fminf(fmaxf(rintf(v * is), -4.0f), 3.0f);
                a += fast_ex2(fmaf(2.4f, fast_lg2(fabsf(fmaf(s, r, -v))), B));
            }
            #pragma unroll
            for (int o = 16; o > 0; o >>= 1) a += __shfl_xor_sync(0xffffffffu, a, o);
            if (lane == 0) serr[c * 8 + wid] = a;
        }
    }
    __syncthreads();

    if (tid < NCAND) {
        float t = 0.0f;
        #pragma unroll
        for (int k = 0; k < 8; k++) t += serr[tid * 8 + k];
        stot[tid] = t;
    }
    __syncthreads();

    if (tid == 0) {
        float best = stot[0];
        int bi = 0;
        for (int c = 1; c < NCAND; c++) {
            float e = stot[c];
            if (e < best) { best = e; bi = c; }
        }
        sscale = sS[bi];
    }
    __syncthreads();

    // ---- Final dequant (re-read row from gmem) ----
    const float s    = sscale;
    const float invs = 1.0f / s;
    float* __restrict__ orow = out + (size_t)row * NCOLS;
    #pragma unroll
    for (int k = 0; k < EPT; k++) {
        float v = wrow[tid + k * NTHREADS];
        float r = rintf(v * invs);
        r = fminf(fmaxf(r, -4.0f), 3.0f);
        orow[tid + k * NTHREADS] = s * r;
    }
}

extern "C" void kernel_launch(void* const* d_in, const int* in_sizes, int n_in,
                              void* d_out, int out_size) {
    (void)in_sizes; (void)n_in; (void)out_size;
    const float* w = (const float*)d_in[0];
    float* out = (float*)d_out;
    quant_search_kernel<<<NROWS, NTHREADS>>>(w, out);
}

// round 9
// speedup vs baseline: 1.1319x; 1.0972x over previous
#include <cuda_runtime.h>

// w: [4096, 4096] fp32. Hinv1 dead (LAMBDA=1.0), bit_width fixed at 3.
#define NROWS 4096
#define NCOLS 4096
#define NTHREADS 256
#define EPT (NCOLS / NTHREADS)
#define NCAND 101

__device__ __forceinline__ float fast_lg2(float x) {
    float y; asm("lg2.approx.f32 %0, %1;" : "=f"(y) : "f"(x)); return y;
}
__device__ __forceinline__ float fast_ex2(float x) {
    float y; asm("ex2.approx.f32 %0, %1;" : "=f"(y) : "f"(x)); return y;
}

// ---- packed f32x2 helpers (Blackwell sm_103a) ----
__device__ __forceinline__ unsigned long long pk2(float lo, float hi) {
    unsigned long long o;
    asm("mov.b64 %0, {%1, %2};" : "=l"(o) : "f"(lo), "f"(hi));
    return o;
}
__device__ __forceinline__ void upk2(float& lo, float& hi, unsigned long long p) {
    asm("mov.b64 {%0, %1}, %2;" : "=f"(lo), "=f"(hi) : "l"(p));
}
__device__ __forceinline__ unsigned long long mul2(unsigned long long a, unsigned long long b) {
    unsigned long long o;
    asm("mul.rn.f32x2 %0, %1, %2;" : "=l"(o) : "l"(a), "l"(b));
    return o;
}
__device__ __forceinline__ unsigned long long add2(unsigned long long a, unsigned long long b) {
    unsigned long long o;
    asm("add.rn.f32x2 %0, %1, %2;" : "=l"(o) : "l"(a), "l"(b));
    return o;
}
__device__ __forceinline__ unsigned long long sub2(unsigned long long a, unsigned long long b) {
    unsigned long long o;
    asm("sub.rn.f32x2 %0, %1, %2;" : "=l"(o) : "l"(a), "l"(b));
    return o;
}
__device__ __forceinline__ unsigned long long fma2(unsigned long long a, unsigned long long b,
                                                   unsigned long long c) {
    unsigned long long o;
    asm("fma.rn.f32x2 %0, %1, %2, %3;" : "=l"(o) : "l"(a), "l"(b), "l"(c));
    return o;
}
__device__ __forceinline__ unsigned long long abs2(unsigned long long a) {
    return a & 0x7FFFFFFF7FFFFFFFull;
}

// ---- f16x2 MUFU helpers ----
__device__ __forceinline__ unsigned cvt_f16x2(float hi, float lo) {
    unsigned r; asm("cvt.rn.f16x2.f32 %0, %1, %2;" : "=r"(r) : "f"(hi), "f"(lo));
    return r;
}
__device__ __forceinline__ unsigned ex2h2(unsigned x) {
    unsigned r; asm("ex2.approx.f16x2 %0, %1;" : "=r"(r) : "r"(x));
    return r;
}
__device__ __forceinline__ void h2_to_f32(float& lo, float& hi, unsigned h) {
    asm("{\n\t.reg .b16 l, u;\n\t"
        "mov.b32 {l, u}, %2;\n\t"
        "cvt.f32.f16 %0, l;\n\t"
        "cvt.f32.f16 %1, u;\n\t}" : "=f"(lo), "=f"(hi) : "r"(h));
}

// Candidate shrink factors in reference scan order.
__device__ __forceinline__ float pcand(int c) {
    const float delta = 0.1f / 50.0f;
    if (c == 0) return 1.0f;
    if (c <= 50) return fmaf(delta, (float)c, 1.0f);
    return fmaf(-delta, (float)(c - 50), 1.0f);
}

#define MAGIC  12582912.0f   // 1.5*2^23 : rint via add/sub
#define MAGIC2 25165824.0f   // 3*2^23   : even-grain magic -> R = 2*rint(q/2)

// Degree-6 Chebyshev-economized poly for x^2.4 on [0,1], abs err <= ~5e-5.
#define PA0  0.0000551f
#define PA1 -0.0078023f
#define PA2  0.3638754f
#define PA3  1.1643678f
#define PA4 -0.9356587f
#define PA5  0.5629952f
#define PA6 -0.1478570f

__global__ __launch_bounds__(NTHREADS, 4) void quant_search_kernel(
    const float* __restrict__ w, float* __restrict__ out)
{
    __shared__ __align__(16) float sact[NCOLS];  // interior front, boundary back
    __shared__ float sS[NCAND];
    __shared__ float sI[NCAND];
    __shared__ float sC[NCAND];                  // (s/2)^2.4 * 2^B per candidate
    __shared__ float serr[NCAND * 8];
    __shared__ float stot[NCAND];
    __shared__ float smn[8], smx[8];
    __shared__ float sscale;
    __shared__ int   scnt_i, scnt_b;

    const int row  = blockIdx.x;
    const int tid  = threadIdx.x;
    const int lane = tid & 31;
    const int wid  = tid >> 5;
    const float* __restrict__ wrow = w + (size_t)row * NCOLS;

    if (tid == 0) { scnt_i = 0; scnt_b = 0; }

    // ---- Load row; min/max vs 0 (reference semantics) ----
    float wv[EPT];
    float mn = 0.0f, mx = 0.0f;
    #pragma unroll
    for (int k = 0; k < EPT; k++) {
        wv[k] = wrow[tid + k * NTHREADS];
        mn = fminf(mn, wv[k]);
        mx = fmaxf(mx, wv[k]);
    }
    #pragma unroll
    for (int o = 16; o > 0; o >>= 1) {
        mn = fminf(mn, __shfl_xor_sync(0xffffffffu, mn, o));
        mx = fmaxf(mx, __shfl_xor_sync(0xffffffffu, mx, o));
    }
    if (lane == 0) { smn[wid] = mn; smx[wid] = mx; }
    __syncthreads();

    float xmin = smn[0], xmax = smx[0];
    #pragma unroll
    for (int k = 1; k < 8; k++) {
        xmin = fminf(xmin, smn[k]);
        xmax = fmaxf(xmax, smx[k]);
    }
    if (xmin == 0.0f && xmax == 0.0f) { xmin = -1.0f; xmax = 1.0f; }
    const float rng = xmax - xmin;

    const float s_min = pcand(NCAND - 1) * rng / 7.0f;
    const float thr_p  = 0.49999f * s_min;   // prune: rint=0 for every candidate
    const float thr_hi = 3.4999f  * s_min;   // interior: clamp can never fire
    const float thr_lo = -4.4999f * s_min;

    // Per-row exponent bias (argmin-invariant global factor 2^B).
    const float B = fmaf(-2.4f, fast_lg2(rng), 11.5376f);

    if (tid < NCAND) {
        float s = pcand(tid) * rng / 7.0f;
        sS[tid] = s;
        sI[tid] = 1.0f / s;
        sC[tid] = fast_ex2(fmaf(2.4f, fast_lg2(0.5f * s), B));  // (s/2)^2.4 * 2^B
    }

    // ---- Two-class compaction (order irrelevant to fp-tolerant argmin) ----
    int ci = 0, cb = 0;
    #pragma unroll
    for (int k = 0; k < EPT; k++) {
        bool active = fabsf(wv[k]) > thr_p;
        bool inter  = active && (wv[k] < thr_hi) && (wv[k] > thr_lo);
        ci += inter ? 1 : 0;
        cb += (active && !inter) ? 1 : 0;
    }
    int bi_ = (ci > 0) ? atomicAdd(&scnt_i, ci) : 0;
    int bb_ = (cb > 0) ? atomicAdd(&scnt_b, cb) : 0;
    #pragma unroll
    for (int k = 0; k < EPT; k++) {
        bool active = fabsf(wv[k]) > thr_p;
        bool inter  = active && (wv[k] < thr_hi) && (wv[k] > thr_lo);
        if (inter) sact[bi_++] = wv[k];
        else if (active) sact[NCOLS - 1 - (bb_++)] = wv[k];
    }
    __syncthreads();
    const int nint   = scnt_i;
    const int nbnd   = scnt_b;
    const int npairs = nint >> 1;
    const int oddi   = nint & 1;

    const unsigned long long MG  = pk2(MAGIC,  MAGIC);
    const unsigned long long MG2 = pk2(MAGIC2, MAGIC2);
    const unsigned long long A0 = pk2(PA0, PA0), A1 = pk2(PA1, PA1), A2 = pk2(PA2, PA2);
    const unsigned long long A3 = pk2(PA3, PA3), A4 = pk2(PA4, PA4), A5 = pk2(PA5, PA5);
    const unsigned long long A6 = pk2(PA6, PA6);

    // ---- Candidate search: 25 tiles of 4 (3 f16-MUFU + 1 fma-poly), then cand 100
    for (int ct = 0; ct < NCAND - 1; ct += 4) {
        const float s0 = sS[ct],  s1 = sS[ct+1], s2 = sS[ct+2], s3 = sS[ct+3];
        const float i0 = sI[ct],  i1 = sI[ct+1], i2 = sI[ct+2], i3 = sI[ct+3];
        const unsigned long long ii0 = pk2(i0, i0), ii1 = pk2(i1, i1), ii2 = pk2(i2, i2);
        const unsigned long long ns0 = pk2(-s0, -s0), ns1 = pk2(-s1, -s1), ns2 = pk2(-s2, -s2);
        const float j3 = 2.0f * i3;
        const unsigned long long jj3 = pk2(j3, j3);
        unsigned long long ac0 = 0ull, ac1 = 0ull, ac2 = 0ull, p3 = 0ull;

        for (int i = tid; i < npairs; i += NTHREADS) {
            const float2 vp = reinterpret_cast<const float2*>(sact)[i];
            const unsigned long long v2 = pk2(vp.x, vp.y);

            #define F16_STEP(ii, ns, acc) do {                             \
                unsigned long long u = mul2(v2, ii);                       \
                unsigned long long r = sub2(add2(u, MG), MG);              \
                unsigned long long d = fma2(ns, r, v2);                    \
                float dl, dh; upk2(dl, dh, d);                             \
                float x0 = fmaf(2.4f, fast_lg2(fabsf(dl)), B);             \
                float x1 = fmaf(2.4f, fast_lg2(fabsf(dh)), B);             \
                float e0, e1; h2_to_f32(e0, e1, ex2h2(cvt_f16x2(x1, x0))); \
                acc = add2(acc, pk2(e0, e1)); } while (0)
            F16_STEP(ii0, ns0, ac0);
            F16_STEP(ii1, ns1, ac1);
            F16_STEP(ii2, ns2, ac2);
            #undef F16_STEP

            // Poly candidate ct+3: q = 2u; R = 2*rint(u) (even-grain magic);
            // t = q - R = 2(u - r); term = P(|t|), scaled later by sC[ct+3].
            {
                unsigned long long q = mul2(v2, jj3);
                unsigned long long R = sub2(add2(q, MG2), MG2);
                unsigned long long t = sub2(q, R);
                unsigned long long at = abs2(t);
                unsigned long long pp = fma2(A6, at, A5);
                pp = fma2(pp, at, A4); pp = fma2(pp, at, A3);
                pp = fma2(pp, at, A2); pp = fma2(pp, at, A1);
                pp = fma2(pp, at, A0);
                p3 = add2(p3, pp);
            }
        }

        float a0, a1, a2, a3, tl, th;
        upk2(tl, th, ac0); a0 = tl + th;
        upk2(tl, th, ac1); a1 = tl + th;
        upk2(tl, th, ac2); a2 = tl + th;
        upk2(tl, th, p3);  a3 = (tl + th) * sC[ct+3];

        // Boundary (+ odd interior tail): scalar f32 MUFU with clamps, biased.
        for (int j = tid; j < nbnd + oddi; j += NTHREADS) {
            const float v = (j < nbnd) ? sact[NCOLS - 1 - j] : sact[nint - 1];
            float r;
            r = fminf(fmaxf(rintf(v * i0), -4.0f), 3.0f);
            a0 += fast_ex2(fmaf(2.4f, fast_lg2(fabsf(fmaf(s0, r, -v))), B));
            r = fminf(fmaxf(rintf(v * i1), -4.0f), 3.0f);
            a1 += fast_ex2(fmaf(2.4f, fast_lg2(fabsf(fmaf(s1, r, -v))), B));
            r = fminf(fmaxf(rintf(v * i2), -4.0f), 3.0f);
            a2 += fast_ex2(fmaf(2.4f, fast_lg2(fabsf(fmaf(s2, r, -v))), B));
            r = fminf(fmaxf(rintf(v * i3), -4.0f), 3.0f);
            a3 += fast_ex2(fmaf(2.4f, fast_lg2(fabsf(fmaf(s3, r, -v))), B));
        }

        #pragma unroll
        for (int o = 16; o > 0; o >>= 1) {
            a0 += __shfl_xor_sync(0xffffffffu, a0, o);
            a1 += __shfl_xor_sync(0xffffffffu, a1, o);
            a2 += __shfl_xor_sync(0xffffffffu, a2, o);
            a3 += __shfl_xor_sync(0xffffffffu, a3, o);
        }
        if (lane == 0) {
            serr[(ct    ) * 8 + wid] = a0;
            serr[(ct + 1) * 8 + wid] = a1;
            serr[(ct + 2) * 8 + wid] = a2;
            serr[(ct + 3) * 8 + wid] = a3;
        }
    }
    {   // candidate 100: scalar f32 MUFU path, biased
        const int c = NCAND - 1;
        const float s = sS[c], is = sI[c];
        float a = 0.0f;
        for (int i = tid; i < nint; i += NTHREADS) {
            const float v = sact[i];
            float r = rintf(v * is);
            a += fast_ex2(fmaf(2.4f, fast_lg2(fabsf(fmaf(s, r, -v))), B));
        }
        for (int j = tid; j < nbnd; j += NTHREADS) {
            const float v = sact[NCOLS - 1 - j];
            float r = fminf(fmaxf(rintf(v * is), -4.0f), 3.0f);
            a += fast_ex2(fmaf(2.4f, fast_lg2(fabsf(fmaf(s, r, -v))), B));
        }
        #pragma unroll
        for (int o = 16; o > 0; o >>= 1) a += __shfl_xor_sync(0xffffffffu, a, o);
        if (lane == 0) serr[c * 8 + wid] = a;
    }
    __syncthreads();

    if (tid < NCAND) {
        float t = 0.0f;
        #pragma unroll
        for (int k = 0; k < 8; k++) t += serr[tid * 8 + k];
        stot[tid] = t;
    }
    __syncthreads();

    // Sequential argmin, strict '<' => earliest candidate wins ties (scan order)
    if (tid == 0) {
        float best = stot[0];
        int bi = 0;
        for (int c = 1; c < NCAND; c++) {
            float e = stot[c];
            if (e < best) { best = e; bi = c; }
        }
        sscale = sS[bi];
    }
    __syncthreads();

    // ---- Final dequant (re-read row from gmem; DRAM ~2% utilized) ----
    const float s    = sscale;
    const float invs = 1.0f / s;
    float* __restrict__ orow = out + (size_t)row * NCOLS;
    #pragma unroll
    for (int k = 0; k < EPT; k++) {
        float v = wrow[tid + k * NTHREADS];
        float r = rintf(v * invs);
        r = fminf(fmaxf(r, -4.0f), 3.0f);
        orow[tid + k * NTHREADS] = s * r;
    }
}

extern "C" void kernel_launch(void* const* d_in, const int* in_sizes, int n_in,
                              void* d_out, int out_size) {
    (void)in_sizes; (void)n_in; (void)out_size;
    const float* w = (const float*)d_in[0];
    float* out = (float*)d_out;
    quant_search_kernel<<<NROWS, NTHREADS>>>(w, out);
}

// round 10
// speedup vs baseline: 1.1944x; 1.0552x over previous
#include <cuda_runtime.h>

// w: [4096, 4096] fp32. Hinv1 dead (LAMBDA=1.0), bit_width fixed at 3.
#define NROWS 4096
#define NCOLS 4096
#define NTHREADS 256
#define EPT (NCOLS / NTHREADS)
#define NCAND 101

__device__ __forceinline__ float fast_lg2(float x) {
    float y; asm("lg2.approx.f32 %0, %1;" : "=f"(y) : "f"(x)); return y;
}
__device__ __forceinline__ float fast_ex2(float x) {
    float y; asm("ex2.approx.f32 %0, %1;" : "=f"(y) : "f"(x)); return y;
}

// ---- packed f32x2 helpers (Blackwell sm_103a) ----
__device__ __forceinline__ unsigned long long pk2(float lo, float hi) {
    unsigned long long o;
    asm("mov.b64 %0, {%1, %2};" : "=l"(o) : "f"(lo), "f"(hi));
    return o;
}
__device__ __forceinline__ void upk2(float& lo, float& hi, unsigned long long p) {
    asm("mov.b64 {%0, %1}, %2;" : "=f"(lo), "=f"(hi) : "l"(p));
}
__device__ __forceinline__ unsigned long long mul2(unsigned long long a, unsigned long long b) {
    unsigned long long o;
    asm("mul.rn.f32x2 %0, %1, %2;" : "=l"(o) : "l"(a), "l"(b));
    return o;
}
__device__ __forceinline__ unsigned long long add2(unsigned long long a, unsigned long long b) {
    unsigned long long o;
    asm("add.rn.f32x2 %0, %1, %2;" : "=l"(o) : "l"(a), "l"(b));
    return o;
}
__device__ __forceinline__ unsigned long long sub2(unsigned long long a, unsigned long long b) {
    unsigned long long o;
    asm("sub.rn.f32x2 %0, %1, %2;" : "=l"(o) : "l"(a), "l"(b));
    return o;
}
__device__ __forceinline__ unsigned long long fma2(unsigned long long a, unsigned long long b,
                                                   unsigned long long c) {
    unsigned long long o;
    asm("fma.rn.f32x2 %0, %1, %2, %3;" : "=l"(o) : "l"(a), "l"(b), "l"(c));
    return o;
}
__device__ __forceinline__ unsigned long long abs2(unsigned long long a) {
    return a & 0x7FFFFFFF7FFFFFFFull;
}

// ---- f16x2 helpers ----
__device__ __forceinline__ unsigned cvt_f16x2(float hi, float lo) {
    unsigned r; asm("cvt.rn.f16x2.f32 %0, %1, %2;" : "=r"(r) : "f"(hi), "f"(lo));
    return r;
}
__device__ __forceinline__ unsigned ex2h2(unsigned x) {
    unsigned r; asm("ex2.approx.f16x2 %0, %1;" : "=r"(r) : "r"(x));
    return r;
}
__device__ __forceinline__ unsigned hadd2(unsigned a, unsigned b) {
    unsigned o; asm("add.rn.f16x2 %0, %1, %2;" : "=r"(o) : "r"(a), "r"(b));
    return o;
}
__device__ __forceinline__ void h2_to_f32(float& lo, float& hi, unsigned h) {
    asm("{\n\t.reg .b16 l, u;\n\t"
        "mov.b32 {l, u}, %2;\n\t"
        "cvt.f32.f16 %0, l;\n\t"
        "cvt.f32.f16 %1, u;\n\t}" : "=f"(lo), "=f"(hi) : "r"(h));
}

// Candidate shrink factors in reference scan order.
__device__ __forceinline__ float pcand(int c) {
    const float delta = 0.1f / 50.0f;
    if (c == 0) return 1.0f;
    if (c <= 50) return fmaf(delta, (float)c, 1.0f);
    return fmaf(-delta, (float)(c - 50), 1.0f);
}

#define MAGIC  12582912.0f   // 1.5*2^23 : rint via add/sub
#define MAGIC2 25165824.0f   // 3*2^23   : even-grain magic -> R = 2*rint(q/2)

// Degree-6 Chebyshev-economized poly for x^2.4 on [0,1], abs err <= ~5e-5.
#define PA0  0.0000551f
#define PA1 -0.0078023f
#define PA2  0.3638754f
#define PA3  1.1643678f
#define PA4 -0.9356587f
#define PA5  0.5629952f
#define PA6 -0.1478570f

__global__ __launch_bounds__(NTHREADS, 4) void quant_search_kernel(
    const float* __restrict__ w, float* __restrict__ out)
{
    __shared__ __align__(16) float sact[NCOLS];  // interior front, boundary back
    __shared__ float sS[NCAND];
    __shared__ float sI[NCAND];
    __shared__ float sC[NCAND];                  // (s/2)^2.4 * 2^B per candidate
    __shared__ float serr[NCAND * 8];
    __shared__ float stot[NCAND];
    __shared__ float smn[8], smx[8];
    __shared__ float sscale;
    __shared__ int   scnt_i, scnt_b;

    const int row  = blockIdx.x;
    const int tid  = threadIdx.x;
    const int lane = tid & 31;
    const int wid  = tid >> 5;
    const float* __restrict__ wrow = w + (size_t)row * NCOLS;

    if (tid == 0) { scnt_i = 0; scnt_b = 0; }

    // ---- Load row; min/max vs 0 (reference semantics) ----
    float wv[EPT];
    float mn = 0.0f, mx = 0.0f;
    #pragma unroll
    for (int k = 0; k < EPT; k++) {
        wv[k] = wrow[tid + k * NTHREADS];
        mn = fminf(mn, wv[k]);
        mx = fmaxf(mx, wv[k]);
    }
    #pragma unroll
    for (int o = 16; o > 0; o >>= 1) {
        mn = fminf(mn, __shfl_xor_sync(0xffffffffu, mn, o));
        mx = fmaxf(mx, __shfl_xor_sync(0xffffffffu, mx, o));
    }
    if (lane == 0) { smn[wid] = mn; smx[wid] = mx; }
    __syncthreads();

    float xmin = smn[0], xmax = smx[0];
    #pragma unroll
    for (int k = 1; k < 8; k++) {
        xmin = fminf(xmin, smn[k]);
        xmax = fmaxf(xmax, smx[k]);
    }
    if (xmin == 0.0f && xmax == 0.0f) { xmin = -1.0f; xmax = 1.0f; }
    const float rng = xmax - xmin;

    const float s_min = pcand(NCAND - 1) * rng / 7.0f;
    const float thr_p  = 0.49999f * s_min;   // prune: rint=0 for every candidate
    const float thr_hi = 3.4999f  * s_min;   // interior: clamp can never fire
    const float thr_lo = -4.4999f * s_min;

    // Per-row exponent bias (argmin-invariant global factor 2^B).
    const float B = fmaf(-2.4f, fast_lg2(rng), 11.5376f);
    const unsigned hB = cvt_f16x2(B, B);     // packed f16 bias (error is 2^dB, global)

    if (tid < NCAND) {
        float s = pcand(tid) * rng / 7.0f;
        sS[tid] = s;
        sI[tid] = 1.0f / s;
        sC[tid] = fast_ex2(fmaf(2.4f, fast_lg2(0.5f * s), B));  // (s/2)^2.4 * 2^B
    }

    // ---- Two-class compaction (order irrelevant to fp-tolerant argmin) ----
    int ci = 0, cb = 0;
    #pragma unroll
    for (int k = 0; k < EPT; k++) {
        bool active = fabsf(wv[k]) > thr_p;
        bool inter  = active && (wv[k] < thr_hi) && (wv[k] > thr_lo);
        ci += inter ? 1 : 0;
        cb += (active && !inter) ? 1 : 0;
    }
    int bi_ = (ci > 0) ? atomicAdd(&scnt_i, ci) : 0;
    int bb_ = (cb > 0) ? atomicAdd(&scnt_b, cb) : 0;
    #pragma unroll
    for (int k = 0; k < EPT; k++) {
        bool active = fabsf(wv[k]) > thr_p;
        bool inter  = active && (wv[k] < thr_hi) && (wv[k] > thr_lo);
        if (inter) sact[bi_++] = wv[k];
        else if (active) sact[NCOLS - 1 - (bb_++)] = wv[k];
    }
    __syncthreads();
    const int nint   = scnt_i;
    const int nbnd   = scnt_b;
    const int npairs = nint >> 1;
    const int oddi   = nint & 1;

    const unsigned long long MG  = pk2(MAGIC,  MAGIC);
    const unsigned long long MG2 = pk2(MAGIC2, MAGIC2);
    const unsigned long long A0 = pk2(PA0, PA0), A1 = pk2(PA1, PA1), A2 = pk2(PA2, PA2);
    const unsigned long long A3 = pk2(PA3, PA3), A4 = pk2(PA4, PA4), A5 = pk2(PA5, PA5);
    const unsigned long long A6 = pk2(PA6, PA6);

    // ---- Candidate search: 25 tiles of 4 (3 f16-MUFU + 1 fma-poly), then cand 100
    for (int ct = 0; ct < NCAND - 1; ct += 4) {
        const float s0 = sS[ct],  s1 = sS[ct+1], s2 = sS[ct+2], s3 = sS[ct+3];
        const float i0 = sI[ct],  i1 = sI[ct+1], i2 = sI[ct+2], i3 = sI[ct+3];
        const unsigned long long ii0 = pk2(i0, i0), ii1 = pk2(i1, i1), ii2 = pk2(i2, i2);
        const unsigned long long ns0 = pk2(-s0, -s0), ns1 = pk2(-s1, -s1), ns2 = pk2(-s2, -s2);
        const float j3 = 2.0f * i3;
        const unsigned long long jj3 = pk2(j3, j3);
        unsigned hc0 = 0u, hc1 = 0u, hc2 = 0u;     // f16x2 accumulators
        unsigned long long p3 = 0ull;

        for (int i = tid; i < npairs; i += NTHREADS) {
            const float2 vp = reinterpret_cast<const float2*>(sact)[i];
            const unsigned long long v2 = pk2(vp.x, vp.y);

            // f16 path: term = ex2_h16(2.4*lg2|d| + B), accumulated in f16x2.
            #define F16_STEP(ii, ns, acc) do {                             \
                unsigned long long u = mul2(v2, ii);                       \
                unsigned long long r = sub2(add2(u, MG), MG);              \
                unsigned long long d = fma2(ns, r, v2);                    \
                float dl, dh; upk2(dl, dh, d);                             \
                float x0 = 2.4f * fast_lg2(fabsf(dl));                     \
                float x1 = 2.4f * fast_lg2(fabsf(dh));                     \
                unsigned hx = hadd2(cvt_f16x2(x1, x0), hB);                \
                acc = hadd2(acc, ex2h2(hx)); } while (0)
            F16_STEP(ii0, ns0, hc0);
            F16_STEP(ii1, ns1, hc1);
            F16_STEP(ii2, ns2, hc2);
            #undef F16_STEP

            // Poly candidate ct+3: q = 2u; R = 2*rint(u) (even-grain magic);
            // t = q - R = 2(u - r); term = P(|t|), scaled later by sC[ct+3].
            {
                unsigned long long q = mul2(v2, jj3);
                unsigned long long R = sub2(add2(q, MG2), MG2);
                unsigned long long t = sub2(q, R);
                unsigned long long at = abs2(t);
                unsigned long long pp = fma2(A6, at, A5);
                pp = fma2(pp, at, A4); pp = fma2(pp, at, A3);
                pp = fma2(pp, at, A2); pp = fma2(pp, at, A1);
                pp = fma2(pp, at, A0);
                p3 = add2(p3, pp);
            }
        }

        float a0, a1, a2, a3, tl, th;
        h2_to_f32(tl, th, hc0); a0 = tl + th;
        h2_to_f32(tl, th, hc1); a1 = tl + th;
        h2_to_f32(tl, th, hc2); a2 = tl + th;
        upk2(tl, th, p3);       a3 = (tl + th) * sC[ct+3];

        // Boundary (+ odd interior tail): scalar f32 MUFU with clamps, biased.
        for (int j = tid; j < nbnd + oddi; j += NTHREADS) {
            const float v = (j < nbnd) ? sact[NCOLS - 1 - j] : sact[nint - 1];
            float r;
            r = fminf(fmaxf(rintf(v * i0), -4.0f), 3.0f);
            a0 += fast_ex2(fmaf(2.4f, fast_lg2(fabsf(fmaf(s0, r, -v))), B));
            r = fminf(fmaxf(rintf(v * i1), -4.0f), 3.0f);
            a1 += fast_ex2(fmaf(2.4f, fast_lg2(fabsf(fmaf(s1, r, -v))), B));
            r = fminf(fmaxf(rintf(v * i2), -4.0f), 3.0f);
            a2 += fast_ex2(fmaf(2.4f, fast_lg2(fabsf(fmaf(s2, r, -v))), B));
            r = fminf(fmaxf(rintf(v * i3), -4.0f), 3.0f);
            a3 += fast_ex2(fmaf(2.4f, fast_lg2(fabsf(fmaf(s3, r, -v))), B));
        }

        #pragma unroll
        for (int o = 16; o > 0; o >>= 1) {
            a0 += __shfl_xor_sync(0xffffffffu, a0, o);
            a1 += __shfl_xor_sync(0xffffffffu, a1, o);
            a2 += __shfl_xor_sync(0xffffffffu, a2, o);
            a3 += __shfl_xor_sync(0xffffffffu, a3, o);
        }
        if (lane == 0) {
            serr[(ct    ) * 8 + wid] = a0;
            serr[(ct + 1) * 8 + wid] = a1;
            serr[(ct + 2) * 8 + wid] = a2;
            serr[(ct + 3) * 8 + wid] = a3;
        }
    }
    {   // candidate 100: scalar f32 MUFU path, biased
        const int c = NCAND - 1;
        const float s = sS[c], is = sI[c];
        float a = 0.0f;
        for (int i = tid; i < nint; i += NTHREADS) {
            const float v = sact[i];
            float r = rintf(v * is);
            a += fast_ex2(fmaf(2.4f, fast_lg2(fabsf(fmaf(s, r, -v))), B));
        }
        for (int j = tid; j < nbnd; j += NTHREADS) {
            const float v = sact[NCOLS - 1 - j];
            float r = fminf(fmaxf(rintf(v * is), -4.0f), 3.0f);
            a += fast_ex2(fmaf(2.4f, fast_lg2(fabsf(fmaf(s, r, -v))), B));
        }
        #pragma unroll
        for (int o = 16; o > 0; o >>= 1) a += __shfl_xor_sync(0xffffffffu, a, o);
        if (lane == 0) serr[c * 8 + wid] = a;
    }
    __syncthreads();

    if (tid < NCAND) {
        float t = 0.0f;
        #pragma unroll
        for (int k = 0; k < 8; k++) t += serr[tid * 8 + k];
        stot[tid] = t;
    }
    __syncthreads();

    // Sequential argmin, strict '<' => earliest candidate wins ties (scan order)
    if (tid == 0) {
        float best = stot[0];
        int bi = 0;
        for (int c = 1; c < NCAND; c++) {
            float e = stot[c];
            if (e < best) { best = e; bi = c; }
        }
        sscale = sS[bi];
    }
    __syncthreads();

    // ---- Final dequant (re-read row from gmem; DRAM ~2% utilized) ----
    const float s    = sscale;
    const float invs = 1.0f / s;
    float* __restrict__ orow = out + (size_t)row * NCOLS;
    #pragma unroll
    for (int k = 0; k < EPT; k++) {
        float v = wrow[tid + k * NTHREADS];
        float r = rintf(v * invs);
        r = fminf(fmaxf(r, -4.0f), 3.0f);
        orow[tid + k * NTHREADS] = s * r;
    }
}

extern "C" void kernel_launch(void* const* d_in, const int* in_sizes, int n_in,
                              void* d_out, int out_size) {
    (void)in_sizes; (void)n_in; (void)out_size;
    const float* w = (const float*)d_in[0];
    float* out = (float*)d_out;
    quant_search_kernel<<<NROWS, NTHREADS>>>(w, out);
}

// round 11
// speedup vs baseline: 1.2989x; 1.0875x over previous
#include <cuda_runtime.h>

// w: [4096, 4096] fp32. Hinv1 dead (LAMBDA=1.0), bit_width fixed at 3.
#define NROWS 4096
#define NCOLS 4096
#define NTHREADS 256
#define EPT (NCOLS / NTHREADS)
#define NCAND 101

__device__ __forceinline__ float fast_lg2(float x) {
    float y; asm("lg2.approx.f32 %0, %1;" : "=f"(y) : "f"(x)); return y;
}
__device__ __forceinline__ float fast_ex2(float x) {
    float y; asm("ex2.approx.f32 %0, %1;" : "=f"(y) : "f"(x)); return y;
}

// ---- packed f32x2 helpers (Blackwell sm_103a) ----
__device__ __forceinline__ unsigned long long pk2(float lo, float hi) {
    unsigned long long o;
    asm("mov.b64 %0, {%1, %2};" : "=l"(o) : "f"(lo), "f"(hi));
    return o;
}
__device__ __forceinline__ void upk2(float& lo, float& hi, unsigned long long p) {
    asm("mov.b64 {%0, %1}, %2;" : "=f"(lo), "=f"(hi) : "l"(p));
}
__device__ __forceinline__ unsigned long long mul2(unsigned long long a, unsigned long long b) {
    unsigned long long o;
    asm("mul.rn.f32x2 %0, %1, %2;" : "=l"(o) : "l"(a), "l"(b));
    return o;
}
__device__ __forceinline__ unsigned long long add2(unsigned long long a, unsigned long long b) {
    unsigned long long o;
    asm("add.rn.f32x2 %0, %1, %2;" : "=l"(o) : "l"(a), "l"(b));
    return o;
}
__device__ __forceinline__ unsigned long long sub2(unsigned long long a, unsigned long long b) {
    unsigned long long o;
    asm("sub.rn.f32x2 %0, %1, %2;" : "=l"(o) : "l"(a), "l"(b));
    return o;
}
__device__ __forceinline__ unsigned long long fma2(unsigned long long a, unsigned long long b,
                                                   unsigned long long c) {
    unsigned long long o;
    asm("fma.rn.f32x2 %0, %1, %2, %3;" : "=l"(o) : "l"(a), "l"(b), "l"(c));
    return o;
}
__device__ __forceinline__ unsigned long long abs2(unsigned long long a) {
    return a & 0x7FFFFFFF7FFFFFFFull;
}

// ---- f16x2 helpers ----
__device__ __forceinline__ unsigned cvt_f16x2(float hi, float lo) {
    unsigned r; asm("cvt.rn.f16x2.f32 %0, %1, %2;" : "=r"(r) : "f"(hi), "f"(lo));
    return r;
}
__device__ __forceinline__ unsigned ex2h2(unsigned x) {
    unsigned r; asm("ex2.approx.f16x2 %0, %1;" : "=r"(r) : "r"(x));
    return r;
}
__device__ __forceinline__ unsigned hadd2(unsigned a, unsigned b) {
    unsigned o; asm("add.rn.f16x2 %0, %1, %2;" : "=r"(o) : "r"(a), "r"(b));
    return o;
}
__device__ __forceinline__ void h2_to_f32(float& lo, float& hi, unsigned h) {
    asm("{\n\t.reg .b16 l, u;\n\t"
        "mov.b32 {l, u}, %2;\n\t"
        "cvt.f32.f16 %0, l;\n\t"
        "cvt.f32.f16 %1, u;\n\t}" : "=f"(lo), "=f"(hi) : "r"(h));
}

// Candidate shrink factors in reference scan order.
__device__ __forceinline__ float pcand(int c) {
    const float delta = 0.1f / 50.0f;
    if (c == 0) return 1.0f;
    if (c <= 50) return fmaf(delta, (float)c, 1.0f);
    return fmaf(-delta, (float)(c - 50), 1.0f);
}

#define MAGIC  12582912.0f   // 1.5*2^23 : rint via add/sub
#define MAGIC2 25165824.0f   // 3*2^23   : even-grain magic -> R = 2*rint(q/2)

// Degree-4 Chebyshev truncation of x^2.4 on [0,1], abs err <= ~4e-4
// (derived from the closed-form Chebyshev series; c5~2.3e-4, c6~-7e-5 dropped).
#define Q0  0.000403f
#define Q1 -0.024680f
#define Q2  0.517810f
#define Q3  0.644350f
#define Q4 -0.138060f

__global__ __launch_bounds__(NTHREADS, 4) void quant_search_kernel(
    const float* __restrict__ w, float* __restrict__ out)
{
    __shared__ __align__(16) float sact[NCOLS];  // interior front, boundary back
    __shared__ float sS[NCAND];
    __shared__ float sI[NCAND];
    __shared__ float sC[NCAND];                  // (s/2)^2.4 * 2^B per candidate
    __shared__ float serr[NCAND * 8];
    __shared__ float stot[NCAND];
    __shared__ float smn[8], smx[8];
    __shared__ float sscale;
    __shared__ int   scnt_i, scnt_b;

    const int row  = blockIdx.x;
    const int tid  = threadIdx.x;
    const int lane = tid & 31;
    const int wid  = tid >> 5;
    const float* __restrict__ wrow = w + (size_t)row * NCOLS;

    if (tid == 0) { scnt_i = 0; scnt_b = 0; }

    // ---- Load row; min/max vs 0 (reference semantics) ----
    float wv[EPT];
    float mn = 0.0f, mx = 0.0f;
    #pragma unroll
    for (int k = 0; k < EPT; k++) {
        wv[k] = wrow[tid + k * NTHREADS];
        mn = fminf(mn, wv[k]);
        mx = fmaxf(mx, wv[k]);
    }
    #pragma unroll
    for (int o = 16; o > 0; o >>= 1) {
        mn = fminf(mn, __shfl_xor_sync(0xffffffffu, mn, o));
        mx = fmaxf(mx, __shfl_xor_sync(0xffffffffu, mx, o));
    }
    if (lane == 0) { smn[wid] = mn; smx[wid] = mx; }
    __syncthreads();

    float xmin = smn[0], xmax = smx[0];
    #pragma unroll
    for (int k = 1; k < 8; k++) {
        xmin = fminf(xmin, smn[k]);
        xmax = fmaxf(xmax, smx[k]);
    }
    if (xmin == 0.0f && xmax == 0.0f) { xmin = -1.0f; xmax = 1.0f; }
    const float rng = xmax - xmin;

    const float s_min = pcand(NCAND - 1) * rng / 7.0f;
    const float thr_p  = 0.49999f * s_min;   // prune: rint=0 for every candidate
    const float thr_hi = 3.4999f  * s_min;   // interior: clamp can never fire
    const float thr_lo = -4.4999f * s_min;

    // Per-row exponent bias (argmin-invariant global factor 2^B).
    const float B = fmaf(-2.4f, fast_lg2(rng), 11.5376f);
    const unsigned hB = cvt_f16x2(B, B);     // packed f16 bias (error is 2^dB, global)

    if (tid < NCAND) {
        float s = pcand(tid) * rng / 7.0f;
        sS[tid] = s;
        sI[tid] = 1.0f / s;
        sC[tid] = fast_ex2(fmaf(2.4f, fast_lg2(0.5f * s), B));  // (s/2)^2.4 * 2^B
    }

    // ---- Two-class compaction (order irrelevant to fp-tolerant argmin) ----
    int ci = 0, cb = 0;
    #pragma unroll
    for (int k = 0; k < EPT; k++) {
        bool active = fabsf(wv[k]) > thr_p;
        bool inter  = active && (wv[k] < thr_hi) && (wv[k] > thr_lo);
        ci += inter ? 1 : 0;
        cb += (active && !inter) ? 1 : 0;
    }
    int bi_ = (ci > 0) ? atomicAdd(&scnt_i, ci) : 0;
    int bb_ = (cb > 0) ? atomicAdd(&scnt_b, cb) : 0;
    #pragma unroll
    for (int k = 0; k < EPT; k++) {
        bool active = fabsf(wv[k]) > thr_p;
        bool inter  = active && (wv[k] < thr_hi) && (wv[k] > thr_lo);
        if (inter) sact[bi_++] = wv[k];
        else if (active) sact[NCOLS - 1 - (bb_++)] = wv[k];
    }
    __syncthreads();
    const int nint   = scnt_i;
    const int nbnd   = scnt_b;
    const int npairs = nint >> 1;
    const int oddi   = nint & 1;

    const unsigned long long MG  = pk2(MAGIC,  MAGIC);
    const unsigned long long MG2 = pk2(MAGIC2, MAGIC2);
    const unsigned long long C0 = pk2(Q0, Q0), C1 = pk2(Q1, Q1), C2 = pk2(Q2, Q2);
    const unsigned long long C3 = pk2(Q3, Q3), C4 = pk2(Q4, Q4);

    // ---- Candidate search: 25 tiles of 4 (2 f16-MUFU + 2 fma-poly-d4), then cand 100
    for (int ct = 0; ct < NCAND - 1; ct += 4) {
        const float s0 = sS[ct],  s1 = sS[ct+1], s2 = sS[ct+2], s3 = sS[ct+3];
        const float i0 = sI[ct],  i1 = sI[ct+1], i2 = sI[ct+2], i3 = sI[ct+3];
        const unsigned long long ii0 = pk2(i0, i0), ii1 = pk2(i1, i1);
        const unsigned long long ns0 = pk2(-s0, -s0), ns1 = pk2(-s1, -s1);
        const float j2 = 2.0f * i2, j3 = 2.0f * i3;
        const unsigned long long jj2 = pk2(j2, j2), jj3 = pk2(j3, j3);
        unsigned hc0 = 0u, hc1 = 0u;                 // f16x2 accumulators
        unsigned long long p2 = 0ull, p3 = 0ull;     // f32x2 poly accumulators

        for (int i = tid; i < npairs; i += NTHREADS) {
            const float2 vp = reinterpret_cast<const float2*>(sact)[i];
            const unsigned long long v2 = pk2(vp.x, vp.y);

            // f16 path: term = ex2_h16(2.4*lg2|d| + B), accumulated in f16x2.
            #define F16_STEP(ii, ns, acc) do {                             \
                unsigned long long u = mul2(v2, ii);                       \
                unsigned long long r = sub2(add2(u, MG), MG);              \
                unsigned long long d = fma2(ns, r, v2);                    \
                float dl, dh; upk2(dl, dh, d);                             \
                float x0 = 2.4f * fast_lg2(fabsf(dl));                     \
                float x1 = 2.4f * fast_lg2(fabsf(dh));                     \
                unsigned hx = hadd2(cvt_f16x2(x1, x0), hB);                \
                acc = hadd2(acc, ex2h2(hx)); } while (0)
            F16_STEP(ii0, ns0, hc0);
            F16_STEP(ii1, ns1, hc1);
            #undef F16_STEP

            // Poly path: q = 2u; R = 2*rint(u) (even-grain magic);
            // t = q - R = 2(u - r); term = P4(|t|), scaled later by sC[c].
            #define POLY_STEP(jj, acc) do {                                \
                unsigned long long q = mul2(v2, jj);                       \
                unsigned long long R = sub2(add2(q, MG2), MG2);            \
                unsigned long long t = sub2(q, R);                         \
                unsigned long long at = abs2(t);                           \
                unsigned long long pp = fma2(C4, at, C3);                  \
                pp = fma2(pp, at, C2);                                     \
                pp = fma2(pp, at, C1);                                     \
                pp = fma2(pp, at, C0);                                     \
                acc = add2(acc, pp); } while (0)
            POLY_STEP(jj2, p2);
            POLY_STEP(jj3, p3);
            #undef POLY_STEP
        }

        float a0, a1, a2, a3, tl, th;
        h2_to_f32(tl, th, hc0); a0 = tl + th;
        h2_to_f32(tl, th, hc1); a1 = tl + th;
        upk2(tl, th, p2);       a2 = (tl + th) * sC[ct+2];
        upk2(tl, th, p3);       a3 = (tl + th) * sC[ct+3];

        // Boundary (+ odd interior tail): scalar f32 MUFU with clamps, biased.
        for (int j = tid; j < nbnd + oddi; j += NTHREADS) {
            const float v = (j < nbnd) ? sact[NCOLS - 1 - j] : sact[nint - 1];
            float r;
            r = fminf(fmaxf(rintf(v * i0), -4.0f), 3.0f);
            a0 += fast_ex2(fmaf(2.4f, fast_lg2(fabsf(fmaf(s0, r, -v))), B));
            r = fminf(fmaxf(rintf(v * i1), -4.0f), 3.0f);
            a1 += fast_ex2(fmaf(2.4f, fast_lg2(fabsf(fmaf(s1, r, -v))), B));
            r = fminf(fmaxf(rintf(v * i2), -4.0f), 3.0f);
            a2 += fast_ex2(fmaf(2.4f, fast_lg2(fabsf(fmaf(s2, r, -v))), B));
            r = fminf(fmaxf(rintf(v * i3), -4.0f), 3.0f);
            a3 += fast_ex2(fmaf(2.4f, fast_lg2(fabsf(fmaf(s3, r, -v))), B));
        }

        #pragma unroll
        for (int o = 16; o > 0; o >>= 1) {
            a0 += __shfl_xor_sync(0xffffffffu, a0, o);
            a1 += __shfl_xor_sync(0xffffffffu, a1, o);
            a2 += __shfl_xor_sync(0xffffffffu, a2, o);
            a3 += __shfl_xor_sync(0xffffffffu, a3, o);
        }
        if (lane == 0) {
            serr[(ct    ) * 8 + wid] = a0;
            serr[(ct + 1) * 8 + wid] = a1;
            serr[(ct + 2) * 8 + wid] = a2;
            serr[(ct + 3) * 8 + wid] = a3;
        }
    }
    {   // candidate 100: scalar f32 MUFU path, biased
        const int c = NCAND - 1;
        const float s = sS[c], is = sI[c];
        float a = 0.0f;
        for (int i = tid; i < nint; i += NTHREADS) {
            const float v = sact[i];
            float r = rintf(v * is);
            a += fast_ex2(fmaf(2.4f, fast_lg2(fabsf(fmaf(s, r, -v))), B));
        }
        for (int j = tid; j < nbnd; j += NTHREADS) {
            const float v = sact[NCOLS - 1 - j];
            float r = fminf(fmaxf(rintf(v * is), -4.0f), 3.0f);
            a += fast_ex2(fmaf(2.4f, fast_lg2(fabsf(fmaf(s, r, -v))), B));
        }
        #pragma unroll
        for (int o = 16; o > 0; o >>= 1) a += __shfl_xor_sync(0xffffffffu, a, o);
        if (lane == 0) serr[c * 8 + wid] = a;
    }
    __syncthreads();

    if (tid < NCAND) {
        float t = 0.0f;
        #pragma unroll
        for (int k = 0; k < 8; k++) t += serr[tid * 8 + k];
        stot[tid] = t;
    }
    __syncthreads();

    // Sequential argmin, strict '<' => earliest candidate wins ties (scan order)
    if (tid == 0) {
        float best = stot[0];
        int bi = 0;
        for (int c = 1; c < NCAND; c++) {
            float e = stot[c];
            if (e < best) { best = e; bi = c; }
        }
        sscale = sS[bi];
    }
    __syncthreads();

    // ---- Final dequant (re-read row from gmem; DRAM ~2% utilized) ----
    const float s    = sscale;
    const float invs = 1.0f / s;
    float* __restrict__ orow = out + (size_t)row * NCOLS;
    #pragma unroll
    for (int k = 0; k < EPT; k++) {
        float v = wrow[tid + k * NTHREADS];
        float r = rintf(v * invs);
        r = fminf(fmaxf(r, -4.0f), 3.0f);
        orow[tid + k * NTHREADS] = s * r;
    }
}

extern "C" void kernel_launch(void* const* d_in, const int* in_sizes, int n_in,
                              void* d_out, int out_size) {
    (void)in_sizes; (void)n_in; (void)out_size;
    const float* w = (const float*)d_in[0];
    float* out = (float*)d_out;
    quant_search_kernel<<<NROWS, NTHREADS>>>(w, out);
}